// round 15
// baseline (speedup 1.0000x reference)
#include <cuda_runtime.h>
#include <cstddef>

#define BATCH 16
#define C0    1024
#define C1    512
#define LEN   2048
#define BC    256
#define RC    64
#define NB0   4
#define NB1   2
#define NK    (NB0 + NB1)
#define EPSV  1e-5f
#define NROWS (BATCH * (C0 + C1))
#define NGAP  (BATCH * BC)           // 4096 gap CTAs

// scratch (allocation-free rule: __device__ globals)
__device__ float g_gap[BATCH * BC];
__device__ float g_atten[NK * BATCH * BC];
__device__ int   g_done = 0;         // reset by the last CTA each replay

// ---------------------------------------------------------------------------
// Kernel 1: gap[b][c] = mean over L of block-sums; the LAST finishing CTA
// also computes attention for ALL batches (tiny: 16x256 work on 256 threads)
// and resets the done counter so the graph replays deterministically.
// ---------------------------------------------------------------------------
__global__ __launch_bounds__(256) void gap_atten_kernel(
    const float* __restrict__ x0, const float* __restrict__ x1,
    const float* __restrict__ W_joint, const float* __restrict__ b_joint,
    const float* __restrict__ bn_gamma, const float* __restrict__ bn_beta,
    const float* __restrict__ bn_mean, const float* __restrict__ bn_var,
    const float* __restrict__ W_group, const float* __restrict__ b_group)
{
    const int b = blockIdx.x >> 8;
    const int c = blockIdx.x & (BC - 1);
    const int t = threadIdx.x;

    float sum = 0.0f;

    #pragma unroll
    for (int nb = 0; nb < NB0; nb++) {
        const float4* p = (const float4*)(x0 + (size_t)(b * C0 + nb * BC + c) * LEN);
        float4 v0 = p[t];
        float4 v1 = p[t + 256];
        sum += v0.x + v0.y + v0.z + v0.w;
        sum += v1.x + v1.y + v1.z + v1.w;
    }
    #pragma unroll
    for (int nb = 0; nb < NB1; nb++) {
        const float4* p = (const float4*)(x1 + (size_t)(b * C1 + nb * BC + c) * LEN);
        float4 v0 = p[t];
        float4 v1 = p[t + 256];
        sum += v0.x + v0.y + v0.z + v0.w;
        sum += v1.x + v1.y + v1.z + v1.w;
    }

    __shared__ float red[8];
    __shared__ int   s_last;
    #pragma unroll
    for (int o = 16; o; o >>= 1) sum += __shfl_down_sync(0xffffffffu, sum, o);
    if ((t & 31) == 0) red[t >> 5] = sum;
    __syncthreads();
    if (t == 0) {
        float s = red[0];
        #pragma unroll
        for (int w = 1; w < 8; w++) s += red[w];
        g_gap[b * BC + c] = s * (1.0f / (float)LEN);
        __threadfence();
        s_last = (atomicAdd(&g_done, 1) == NGAP - 1);
    }
    __syncthreads();
    if (!s_last) return;

    // ---------------- last CTA: attention for all batches ----------------
    __threadfence();
    __shared__ __align__(16) float s_gap[BC];
    __shared__ __align__(16) float s_h[RC];

    for (int bb = 0; bb < BATCH; bb++) {
        s_gap[t] = __ldcg(&g_gap[bb * BC + t]);
        __syncthreads();

        if (t < RC) {
            float acc = b_joint[t];
            const float4* w  = (const float4*)(W_joint + t * BC);
            const float4* g4 = (const float4*)s_gap;
            #pragma unroll 4
            for (int c4 = 0; c4 < BC / 4; c4++) {
                float4 wv = w[c4];
                float4 gv = g4[c4];
                acc += wv.x * gv.x + wv.y * gv.y + wv.z * gv.z + wv.w * gv.w;
            }
            acc = (acc - bn_mean[t]) * rsqrtf(bn_var[t] + EPSV) * bn_gamma[t] + bn_beta[t];
            s_h[t] = fmaxf(acc, 0.0f);
        }
        __syncthreads();

        float lg[NK];
        #pragma unroll
        for (int k = 0; k < NK; k++) {
            float acc = b_group[k * BC + t];
            const float4* w = (const float4*)(W_group + (size_t)(k * BC + t) * RC);
            #pragma unroll 4
            for (int r4 = 0; r4 < RC / 4; r4++) {
                float4 wv = w[r4];
                acc += s_h[4 * r4 + 0] * wv.x + s_h[4 * r4 + 1] * wv.y
                     + s_h[4 * r4 + 2] * wv.z + s_h[4 * r4 + 3] * wv.w;
            }
            lg[k] = acc;
        }
        float m = lg[0];
        #pragma unroll
        for (int k = 1; k < NK; k++) m = fmaxf(m, lg[k]);
        float ssum = 0.0f;
        #pragma unroll
        for (int k = 0; k < NK; k++) { lg[k] = expf(lg[k] - m); ssum += lg[k]; }
        const float inv = 1.0f / ssum;
        #pragma unroll
        for (int k = 0; k < NK; k++)
            g_atten[k * (BATCH * BC) + bb * BC + t] = lg[k] * inv;
        __syncthreads();
    }

    if (t == 0) {
        __threadfence();
        g_done = 0;          // reset for next graph replay (deterministic)
    }
}

// ---------------------------------------------------------------------------
// Kernel 2: out = x * atten. One block per row, reversed scan, .cs reads,
// .cs streaming stores (best-measured store policy for this phase).
// ---------------------------------------------------------------------------
__global__ __launch_bounds__(256) void scale_kernel(const float* __restrict__ x0,
                                                    const float* __restrict__ x1,
                                                    float* __restrict__ out) {
    const int row = (NROWS - 1) - blockIdx.x;   // reversed scan
    const int t = threadIdx.x;

    const float4* src;
    float4* dst;
    float scale;

    if (row < BATCH * C0) {
        const int b  = row >> 10;
        const int ch = row & (C0 - 1);
        const int nb = ch >> 8;
        const int c  = ch & (BC - 1);
        scale = __ldg(&g_atten[nb * (BATCH * BC) + b * BC + c]);
        src = (const float4*)(x0 + (size_t)row * LEN);
        dst = (float4*)(out + (size_t)row * LEN);
    } else {
        const int r  = row - BATCH * C0;
        const int b  = r >> 9;
        const int ch = r & (C1 - 1);
        const int nb = ch >> 8;
        const int c  = ch & (BC - 1);
        scale = __ldg(&g_atten[(NB0 + nb) * (BATCH * BC) + b * BC + c]);
        src = (const float4*)(x1 + (size_t)r * LEN);
        dst = (float4*)(out + (size_t)(BATCH * C0) * LEN + (size_t)r * LEN);
    }

    float4 v0 = __ldcs(src + t);
    float4 v1 = __ldcs(src + t + 256);
    v0.x *= scale; v0.y *= scale; v0.z *= scale; v0.w *= scale;
    v1.x *= scale; v1.y *= scale; v1.z *= scale; v1.w *= scale;
    __stcs(dst + t,       v0);
    __stcs(dst + t + 256, v1);
}

// ---------------------------------------------------------------------------
extern "C" void kernel_launch(void* const* d_in, const int* in_sizes, int n_in,
                              void* d_out, int out_size) {
    const float* x0       = (const float*)d_in[0];
    const float* x1       = (const float*)d_in[1];
    const float* W_joint  = (const float*)d_in[2];
    const float* b_joint  = (const float*)d_in[3];
    const float* bn_gamma = (const float*)d_in[4];
    const float* bn_beta  = (const float*)d_in[5];
    const float* bn_mean  = (const float*)d_in[6];
    const float* bn_var   = (const float*)d_in[7];
    const float* W_group  = (const float*)d_in[8];
    const float* b_group  = (const float*)d_in[9];
    float* out = (float*)d_out;

    gap_atten_kernel<<<NGAP, 256>>>(x0, x1, W_joint, b_joint, bn_gamma,
                                    bn_beta, bn_mean, bn_var, W_group, b_group);
    scale_kernel<<<NROWS, 256>>>(x0, x1, out);
}

// round 17
// speedup vs baseline: 3.5364x; 3.5364x over previous
#include <cuda_runtime.h>
#include <cstddef>

#define BATCH 16
#define C0    1024
#define C1    512
#define LEN   2048
#define BC    256
#define RC    64
#define NB0   4
#define NB1   2
#define NK    (NB0 + NB1)
#define EPSV  1e-5f
#define NROWS (BATCH * (C0 + C1))

// scratch (allocation-free rule: __device__ globals)
__device__ float g_gap[BATCH * BC];
__device__ float g_atten[NK * BATCH * BC];

// ---------------------------------------------------------------------------
// Kernel 1: gap[b][c] = mean over L of (sum over NB0 x0-blocks + NB1 x1-blocks)
// One block per (b, c). 6 rows x 2048 f32 = 48 KB per block, float4 loads,
// 12 independent LDG.128 in flight per thread. Runs at the pure-read
// LTS/HBM ceiling (~6.3-6.4 TB/s, ~80% DRAM).
// ---------------------------------------------------------------------------
__global__ __launch_bounds__(256) void gap_kernel(const float* __restrict__ x0,
                                                  const float* __restrict__ x1) {
    const int b = blockIdx.x >> 8;      // / BC
    const int c = blockIdx.x & (BC - 1);
    const int t = threadIdx.x;

    float sum = 0.0f;

    #pragma unroll
    for (int nb = 0; nb < NB0; nb++) {
        const float4* p = (const float4*)(x0 + (size_t)(b * C0 + nb * BC + c) * LEN);
        float4 v0 = p[t];
        float4 v1 = p[t + 256];
        sum += v0.x + v0.y + v0.z + v0.w;
        sum += v1.x + v1.y + v1.z + v1.w;
    }
    #pragma unroll
    for (int nb = 0; nb < NB1; nb++) {
        const float4* p = (const float4*)(x1 + (size_t)(b * C1 + nb * BC + c) * LEN);
        float4 v0 = p[t];
        float4 v1 = p[t + 256];
        sum += v0.x + v0.y + v0.z + v0.w;
        sum += v1.x + v1.y + v1.z + v1.w;
    }

    // block reduction: warp shuffle then cross-warp via shared
    __shared__ float red[8];
    #pragma unroll
    for (int o = 16; o; o >>= 1) sum += __shfl_down_sync(0xffffffffu, sum, o);
    if ((t & 31) == 0) red[t >> 5] = sum;
    __syncthreads();
    if (t < 8) {
        float s = red[t];
        #pragma unroll
        for (int o = 4; o; o >>= 1) s += __shfl_down_sync(0xffu, s, o);
        if (t == 0) g_gap[b * BC + c] = s * (1.0f / (float)LEN);
    }
}

// ---------------------------------------------------------------------------
// Kernel 2: tiny MLP + grouped linear + softmax over blocks.
// One block per batch element b; 256 threads (one per c). 16 parallel CTAs
// keep the uncoalesced W_group row reads latency-hidden (R15 showed a
// single-CTA version of this work is catastrophic).
// ---------------------------------------------------------------------------
__global__ __launch_bounds__(256) void atten_kernel(
    const float* __restrict__ W_joint,   // [RC, BC]
    const float* __restrict__ b_joint,   // [RC]
    const float* __restrict__ bn_gamma,  // [RC]
    const float* __restrict__ bn_beta,   // [RC]
    const float* __restrict__ bn_mean,   // [RC]
    const float* __restrict__ bn_var,    // [RC]
    const float* __restrict__ W_group,   // [NK, BC, RC]
    const float* __restrict__ b_group)   // [NK, BC]
{
    const int b = blockIdx.x;
    const int t = threadIdx.x;

    __shared__ __align__(16) float s_gap[BC];
    __shared__ __align__(16) float s_h[RC];

    s_gap[t] = g_gap[b * BC + t];
    __syncthreads();

    // h[b][r] = relu(BN(gap[b] . W_joint[r] + b_joint[r]))  -- threads 0..63
    if (t < RC) {
        float acc = b_joint[t];
        const float4* w = (const float4*)(W_joint + t * BC);
        const float4* g4 = (const float4*)s_gap;
        #pragma unroll 8
        for (int c4 = 0; c4 < BC / 4; c4++) {
            float4 wv = w[c4];
            float4 gv = g4[c4];
            acc += wv.x * gv.x + wv.y * gv.y + wv.z * gv.z + wv.w * gv.w;
        }
        acc = (acc - bn_mean[t]) * rsqrtf(bn_var[t] + EPSV) * bn_gamma[t] + bn_beta[t];
        s_h[t] = fmaxf(acc, 0.0f);
    }
    __syncthreads();

    // logits[k] for this (b, c=t), then softmax over k
    float lg[NK];
    #pragma unroll
    for (int k = 0; k < NK; k++) {
        float acc = b_group[k * BC + t];
        const float4* w = (const float4*)(W_group + (size_t)(k * BC + t) * RC);
        #pragma unroll
        for (int r4 = 0; r4 < RC / 4; r4++) {
            float4 wv = w[r4];
            acc += s_h[4 * r4 + 0] * wv.x + s_h[4 * r4 + 1] * wv.y
                 + s_h[4 * r4 + 2] * wv.z + s_h[4 * r4 + 3] * wv.w;
        }
        lg[k] = acc;
    }
    float m = lg[0];
    #pragma unroll
    for (int k = 1; k < NK; k++) m = fmaxf(m, lg[k]);
    float ssum = 0.0f;
    #pragma unroll
    for (int k = 0; k < NK; k++) { lg[k] = expf(lg[k] - m); ssum += lg[k]; }
    const float inv = 1.0f / ssum;
    #pragma unroll
    for (int k = 0; k < NK; k++)
        g_atten[k * (BATCH * BC) + b * BC + t] = lg[k] * inv;
}

// ---------------------------------------------------------------------------
// Kernel 3: out = x * atten (broadcast over L). One block per channel row.
// Reversed scan (touch the L2-retained tail of gap's read stream first),
// evict-first streaming loads (.cs) and streaming stores (.cs) -- the
// measured-best store policy (plain 83us / wt ~80us / cs 76us wall).
// ---------------------------------------------------------------------------
__global__ __launch_bounds__(256) void scale_kernel(const float* __restrict__ x0,
                                                    const float* __restrict__ x1,
                                                    float* __restrict__ out) {
    const int row = (NROWS - 1) - blockIdx.x;   // reversed scan
    const int t = threadIdx.x;

    const float4* src;
    float4* dst;
    float scale;

    if (row < BATCH * C0) {
        const int b  = row >> 10;          // / C0
        const int ch = row & (C0 - 1);
        const int nb = ch >> 8;            // / BC
        const int c  = ch & (BC - 1);
        scale = __ldg(&g_atten[nb * (BATCH * BC) + b * BC + c]);
        src = (const float4*)(x0 + (size_t)row * LEN);
        dst = (float4*)(out + (size_t)row * LEN);
    } else {
        const int r  = row - BATCH * C0;
        const int b  = r >> 9;             // / C1
        const int ch = r & (C1 - 1);
        const int nb = ch >> 8;
        const int c  = ch & (BC - 1);
        scale = __ldg(&g_atten[(NB0 + nb) * (BATCH * BC) + b * BC + c]);
        src = (const float4*)(x1 + (size_t)r * LEN);
        dst = (float4*)(out + (size_t)(BATCH * C0) * LEN + (size_t)r * LEN);
    }

    // 512 float4 per row, 256 threads -> 2 each
    float4 v0 = __ldcs(src + t);
    float4 v1 = __ldcs(src + t + 256);
    v0.x *= scale; v0.y *= scale; v0.z *= scale; v0.w *= scale;
    v1.x *= scale; v1.y *= scale; v1.z *= scale; v1.w *= scale;
    __stcs(dst + t,       v0);
    __stcs(dst + t + 256, v1);
}

// ---------------------------------------------------------------------------
extern "C" void kernel_launch(void* const* d_in, const int* in_sizes, int n_in,
                              void* d_out, int out_size) {
    const float* x0       = (const float*)d_in[0];
    const float* x1       = (const float*)d_in[1];
    const float* W_joint  = (const float*)d_in[2];
    const float* b_joint  = (const float*)d_in[3];
    const float* bn_gamma = (const float*)d_in[4];
    const float* bn_beta  = (const float*)d_in[5];
    const float* bn_mean  = (const float*)d_in[6];
    const float* bn_var   = (const float*)d_in[7];
    const float* W_group  = (const float*)d_in[8];
    const float* b_group  = (const float*)d_in[9];
    float* out = (float*)d_out;

    gap_kernel<<<BATCH * BC, 256>>>(x0, x1);
    atten_kernel<<<BATCH, 256>>>(W_joint, b_joint, bn_gamma, bn_beta,
                                 bn_mean, bn_var, W_group, b_group);
    scale_kernel<<<NROWS, 256>>>(x0, x1, out);
}